// round 4
// baseline (speedup 1.0000x reference)
#include <cuda_runtime.h>

// Problem constants: T=4, L=4, N=2048, E=65536, H=64, C=2
#define TT 4
#define LL 4
#define NN 2048
#define EE 65536
#define HH 64
#define TL (TT*LL)

// ---------------- device scratch ----------------
// stride-8 rows (32B aligned): [0..3]={w*xs0,w*xs1,w*ea0,w*ea1}, [4]=w
// Zero at module load; node_kernel restores zeros every call.
__device__ float g_sums[TL * NN * 8];
__device__ float g_val[TT * 2 * LL * NN];   // [T][2*L*N]

// ---------------- K1: edge pass (computes its own alpha coefficients) ----------------
__global__ void __launch_bounds__(256) edge_kernel(const float* __restrict__ x,
                                                   const float* __restrict__ ea,
                                                   const int* __restrict__ src,
                                                   const int* __restrict__ tgt,
                                                   const float* __restrict__ Wq,
                                                   const float* __restrict__ bq,
                                                   const float* __restrict__ Wk,
                                                   const float* __restrict__ bk,
                                                   const float* __restrict__ We)
{
    __shared__ float sc[4][16];         // coefA for (t, l=0..3); t fixed per block

    int tid = threadIdx.x;
    int wid = tid >> 5, lane = tid & 31;
    int idx = blockIdx.x * 256 + tid;   // 0 .. T*E-1
    int t = (blockIdx.x * 256) >> 16;   // constant per block (256 | E)

    // Warps 0..3: compute coefA for tl = t*4 + wid
    if (wid < 4) {
        int tl = t * LL + wid;
        const float* wq0 = Wq + (size_t)tl * 2 * HH;
        const float* wq1 = wq0 + HH;
        const float* bqp = bq + (size_t)tl * HH;
        float q0a = wq0[lane], q0b = wq0[lane + 32];
        float q1a = wq1[lane], q1b = wq1[lane + 32];
        float bba = bqp[lane], bbb = bqp[lane + 32];

        const float* Xs[5];
        Xs[0] = Wk + (size_t)tl * 2 * HH;
        Xs[1] = Xs[0] + HH;
        Xs[2] = We + (size_t)tl * 2 * HH;
        Xs[3] = Xs[2] + HH;
        Xs[4] = bk + (size_t)tl * HH;

        float pa[15];
#pragma unroll
        for (int k = 0; k < 5; k++) {
            float xa = Xs[k][lane], xb = Xs[k][lane + 32];
            pa[3*k + 0] = q0a * xa + q0b * xb;
            pa[3*k + 1] = q1a * xa + q1b * xb;
            pa[3*k + 2] = bba * xa + bbb * xb;
        }
#pragma unroll
        for (int off = 16; off > 0; off >>= 1)
#pragma unroll
            for (int i = 0; i < 15; i++)
                pa[i] += __shfl_down_sync(0xffffffffu, pa[i], off);
        if (lane == 0) {
#pragma unroll
            for (int i = 0; i < 15; i++) sc[wid][i] = pa[i];
            sc[wid][15] = 0.0f;
        }
    }
    __syncthreads();

    int s = src[idx];
    int g = tgt[idx];
    float xs0 = x[2 * s], xs1 = x[2 * s + 1];
    float ea0 = ea[2 * idx], ea1 = ea[2 * idx + 1];
    int tn = t * NN + g;
    float xt0 = x[2 * tn], xt1 = x[2 * tn + 1];

#pragma unroll
    for (int l = 0; l < LL; l++) {
        const float* c = sc[l];
        float A0 = fmaf(c[0],  xt0, fmaf(c[1],  xt1, c[2]));
        float A1 = fmaf(c[3],  xt0, fmaf(c[4],  xt1, c[5]));
        float A2 = fmaf(c[6],  xt0, fmaf(c[7],  xt1, c[8]));
        float A3 = fmaf(c[9],  xt0, fmaf(c[10], xt1, c[11]));
        float A4 = fmaf(c[12], xt0, fmaf(c[13], xt1, c[14]));
        float alpha = (A0 * xs0 + A1 * xs1 + A2 * ea0 + A3 * ea1 + A4) * 0.125f;
        float w = expf(alpha);   // |alpha| is O(1): shift-free softmax is safe
        float* sm = &g_sums[((t * LL + l) * NN + g) * 8];
        asm volatile("red.global.add.v4.f32 [%0], {%1, %2, %3, %4};"
                     :: "l"(sm), "f"(w * xs0), "f"(w * xs1),
                        "f"(w * ea0), "f"(w * ea1)
                     : "memory");
        atomicAdd(sm + 4, w);
    }
}

// ---------------- K2: node pass (computes its own half-sum coefficients) ----------------
__global__ void __launch_bounds__(256) node_kernel(const float* __restrict__ x,
                                                   const float* __restrict__ Wv,
                                                   const float* __restrict__ bv,
                                                   const float* __restrict__ We,
                                                   const float* __restrict__ Wsk,
                                                   const float* __restrict__ bsk)
{
    __shared__ float h[16];             // coefH for this block's tl

    int tid = threadIdx.x;
    int idx = blockIdx.x * 256 + tid;   // 0 .. T*L*N-1
    int tl = (blockIdx.x * 256) >> 11;  // constant per block (256 | N)
    int t = tl >> 2;
    int l = tl & 3;
    int n = idx & (NN - 1);

    if (tid < 32) {
        int lane = tid;
        const float* Ys[8];
        Ys[0] = Wv + (size_t)tl * 2 * HH;
        Ys[1] = Ys[0] + HH;
        Ys[2] = We + (size_t)tl * 2 * HH;
        Ys[3] = Ys[2] + HH;
        Ys[4] = bv + (size_t)tl * HH;
        Ys[5] = Wsk + (size_t)tl * 2 * HH;
        Ys[6] = Ys[5] + HH;
        Ys[7] = bsk + (size_t)tl * HH;

        float ph[16];
#pragma unroll
        for (int k = 0; k < 8; k++) {
            ph[k]     = Ys[k][lane];           // low half (h<32)
            ph[8 + k] = Ys[k][lane + 32];      // high half
        }
#pragma unroll
        for (int off = 16; off > 0; off >>= 1)
#pragma unroll
            for (int i = 0; i < 16; i++)
                ph[i] += __shfl_down_sync(0xffffffffu, ph[i], off);
        if (lane == 0)
#pragma unroll
            for (int i = 0; i < 16; i++) h[i] = ph[i];
    }
    __syncthreads();

    float* smp = &g_sums[idx * 8];
    float4 v = *reinterpret_cast<float4*>(smp);
    float s4 = smp[4];

    // restore zeros for next replay
    *reinterpret_cast<float4*>(smp) = make_float4(0.f, 0.f, 0.f, 0.f);
    smp[4] = 0.f;

    float inv = 1.0f / (s4 + 1e-16f);
    float S0 = v.x * inv, S1 = v.y * inv, S2 = v.z * inv, S3 = v.w * inv;
    float S4 = s4 * inv;

    int tn = t * NN + n;
    float xt0 = x[2 * tn], xt1 = x[2 * tn + 1];

    float P = S0*h[0] + S1*h[1] + S2*h[2] + S3*h[3] + S4*h[4]
            + xt0*h[5] + xt1*h[6] + h[7];
    float Q = S0*h[8] + S1*h[9] + S2*h[10] + S3*h[11] + S4*h[12]
            + xt0*h[13] + xt1*h[14] + h[15];

    int vo = t * (2 * LL * NN) + 2 * (l * NN + n);
    g_val[vo]     = P;
    g_val[vo + 1] = Q;
}

// ---------------- K3: GEMV — 16 warps/block, 1 row/warp, 32KB smem staging ----------------
__global__ void __launch_bounds__(512) gemv_kernel(const float* __restrict__ Wfc,
                                                   const float* __restrict__ bfc,
                                                   float* __restrict__ out)
{
    const int t = blockIdx.y;
    const int row = blockIdx.x * 16 + (threadIdx.x >> 5);
    const int lane = threadIdx.x & 31;
    __shared__ float4 sv[2048];                    // 32 KB = half of val[t]

    const float4* val4 = reinterpret_cast<const float4*>(g_val + t * 16384);
    const float4* W = reinterpret_cast<const float4*>(
        Wfc + ((size_t)(t * 4096 + row)) * 16384);

    float4 a = make_float4(0.f, 0.f, 0.f, 0.f);

#pragma unroll
    for (int c = 0; c < 2; c++) {
        for (int j = threadIdx.x; j < 2048; j += 512)
            sv[j] = val4[c * 2048 + j];
        __syncthreads();

        const float4* Wc = W + c * 2048;
#pragma unroll 8
        for (int j = lane; j < 2048; j += 32) {
            float4 v = sv[j];
            float4 w = Wc[j];
            a.x = fmaf(w.x, v.x, a.x);
            a.y = fmaf(w.y, v.y, a.y);
            a.z = fmaf(w.z, v.z, a.z);
            a.w = fmaf(w.w, v.w, a.w);
        }
        __syncthreads();
    }

    float s = (a.x + a.y) + (a.z + a.w);
#pragma unroll
    for (int off = 16; off > 0; off >>= 1)
        s += __shfl_down_sync(0xffffffffu, s, off);
    if (lane == 0) {
        int o = t * 4096 + row;
        out[o] = s + bfc[o];
    }
}

// ---------------- launch: 3 kernels, single stream ----------------
extern "C" void kernel_launch(void* const* d_in, const int* in_sizes, int n_in,
                              void* d_out, int out_size)
{
    const float* x    = (const float*)d_in[0];
    const float* ea   = (const float*)d_in[1];
    const int*   src  = (const int*)  d_in[2];
    const int*   tgt  = (const int*)  d_in[3];
    const float* Wq   = (const float*)d_in[4];
    const float* bq   = (const float*)d_in[5];
    const float* Wk   = (const float*)d_in[6];
    const float* bk   = (const float*)d_in[7];
    const float* Wv   = (const float*)d_in[8];
    const float* bv   = (const float*)d_in[9];
    const float* We   = (const float*)d_in[10];
    const float* Wsk  = (const float*)d_in[11];
    const float* bsk  = (const float*)d_in[12];
    const float* Wfc  = (const float*)d_in[13];
    const float* bfc  = (const float*)d_in[14];
    float* out = (float*)d_out;

    edge_kernel<<<(TT * EE) / 256, 256>>>(x, ea, src, tgt, Wq, bq, Wk, bk, We);
    node_kernel<<<(TL * NN) / 256, 256>>>(x, Wv, bv, We, Wsk, bsk);
    gemv_kernel<<<dim3(256, TT), 512>>>(Wfc, bfc, out);
}

// round 5
// speedup vs baseline: 1.0484x; 1.0484x over previous
#include <cuda_runtime.h>

// Problem constants: T=4, L=4, N=2048, E=65536, H=64, C=2
#define TT 4
#define LL 4
#define NN 2048
#define EE 65536
#define HH 64
#define TL (TT*LL)

// ---------------- device scratch ----------------
// stride-8 rows (32B aligned): [0..3]={w*xs0,w*xs1,w*ea0,w*ea1}, [4]=w
// Zero at module load; node_kernel restores zeros every call.
__device__ float g_sums[TL * NN * 8];
__device__ float g_val[TT * 2 * LL * NN];   // [T][2*L*N]

// ---------------- K1: edge pass (2 edges/thread, computes own alpha coefs) ----------------
__global__ void __launch_bounds__(256) edge_kernel(const float* __restrict__ x,
                                                   const float* __restrict__ ea,
                                                   const int* __restrict__ src,
                                                   const int* __restrict__ tgt,
                                                   const float* __restrict__ Wq,
                                                   const float* __restrict__ bq,
                                                   const float* __restrict__ Wk,
                                                   const float* __restrict__ bk,
                                                   const float* __restrict__ We)
{
    __shared__ float sc[4][16];         // coefA for (t, l=0..3); t fixed per block

    int tid = threadIdx.x;
    int wid = tid >> 5, lane = tid & 31;
    int base = blockIdx.x * 512;        // 512 edges per block
    int t = base >> 16;                 // constant per block (512 | E)

    // Warps 0..3: compute coefA for tl = t*4 + wid
    if (wid < 4) {
        int tl = t * LL + wid;
        const float* wq0 = Wq + (size_t)tl * 2 * HH;
        const float* wq1 = wq0 + HH;
        const float* bqp = bq + (size_t)tl * HH;
        float q0a = wq0[lane], q0b = wq0[lane + 32];
        float q1a = wq1[lane], q1b = wq1[lane + 32];
        float bba = bqp[lane], bbb = bqp[lane + 32];

        const float* Xs[5];
        Xs[0] = Wk + (size_t)tl * 2 * HH;
        Xs[1] = Xs[0] + HH;
        Xs[2] = We + (size_t)tl * 2 * HH;
        Xs[3] = Xs[2] + HH;
        Xs[4] = bk + (size_t)tl * HH;

        float pa[15];
#pragma unroll
        for (int k = 0; k < 5; k++) {
            float xa = Xs[k][lane], xb = Xs[k][lane + 32];
            pa[3*k + 0] = q0a * xa + q0b * xb;
            pa[3*k + 1] = q1a * xa + q1b * xb;
            pa[3*k + 2] = bba * xa + bbb * xb;
        }
#pragma unroll
        for (int off = 16; off > 0; off >>= 1)
#pragma unroll
            for (int i = 0; i < 15; i++)
                pa[i] += __shfl_down_sync(0xffffffffu, pa[i], off);
        if (lane == 0) {
#pragma unroll
            for (int i = 0; i < 15; i++) sc[wid][i] = pa[i];
            sc[wid][15] = 0.0f;
        }
    }
    __syncthreads();

#pragma unroll
    for (int e = 0; e < 2; e++) {
        int idx = base + e * 256 + tid;
        int s = src[idx];
        int g = tgt[idx];
        float xs0 = x[2 * s], xs1 = x[2 * s + 1];
        float ea0 = ea[2 * idx], ea1 = ea[2 * idx + 1];
        int tn = t * NN + g;
        float xt0 = x[2 * tn], xt1 = x[2 * tn + 1];

#pragma unroll
        for (int l = 0; l < LL; l++) {
            const float* c = sc[l];
            float A0 = fmaf(c[0],  xt0, fmaf(c[1],  xt1, c[2]));
            float A1 = fmaf(c[3],  xt0, fmaf(c[4],  xt1, c[5]));
            float A2 = fmaf(c[6],  xt0, fmaf(c[7],  xt1, c[8]));
            float A3 = fmaf(c[9],  xt0, fmaf(c[10], xt1, c[11]));
            float A4 = fmaf(c[12], xt0, fmaf(c[13], xt1, c[14]));
            float alpha = (A0 * xs0 + A1 * xs1 + A2 * ea0 + A3 * ea1 + A4) * 0.125f;
            float w = expf(alpha);   // |alpha| is O(1): shift-free softmax is safe
            float* sm = &g_sums[((t * LL + l) * NN + g) * 8];
            asm volatile("red.global.add.v4.f32 [%0], {%1, %2, %3, %4};"
                         :: "l"(sm), "f"(w * xs0), "f"(w * xs1),
                            "f"(w * ea0), "f"(w * ea1)
                         : "memory");
            atomicAdd(sm + 4, w);
        }
    }
}

// ---------------- K2: node pass (computes own half-sum coefs, restores zeros) ----------------
__global__ void __launch_bounds__(256) node_kernel(const float* __restrict__ x,
                                                   const float* __restrict__ Wv,
                                                   const float* __restrict__ bv,
                                                   const float* __restrict__ We,
                                                   const float* __restrict__ Wsk,
                                                   const float* __restrict__ bsk)
{
    __shared__ float h[16];             // coefH for this block's tl

    int tid = threadIdx.x;
    int idx = blockIdx.x * 256 + tid;   // 0 .. T*L*N-1
    int tl = (blockIdx.x * 256) >> 11;  // constant per block (256 | N)
    int t = tl >> 2;
    int l = tl & 3;
    int n = idx & (NN - 1);

    if (tid < 32) {
        int lane = tid;
        const float* Ys[8];
        Ys[0] = Wv + (size_t)tl * 2 * HH;
        Ys[1] = Ys[0] + HH;
        Ys[2] = We + (size_t)tl * 2 * HH;
        Ys[3] = Ys[2] + HH;
        Ys[4] = bv + (size_t)tl * HH;
        Ys[5] = Wsk + (size_t)tl * 2 * HH;
        Ys[6] = Ys[5] + HH;
        Ys[7] = bsk + (size_t)tl * HH;

        float ph[16];
#pragma unroll
        for (int k = 0; k < 8; k++) {
            ph[k]     = Ys[k][lane];           // low half (h<32)
            ph[8 + k] = Ys[k][lane + 32];      // high half
        }
#pragma unroll
        for (int off = 16; off > 0; off >>= 1)
#pragma unroll
            for (int i = 0; i < 16; i++)
                ph[i] += __shfl_down_sync(0xffffffffu, ph[i], off);
        if (lane == 0)
#pragma unroll
            for (int i = 0; i < 16; i++) h[i] = ph[i];
    }
    __syncthreads();

    float* smp = &g_sums[idx * 8];
    float4 v = *reinterpret_cast<float4*>(smp);
    float s4 = smp[4];

    // restore zeros for next replay
    *reinterpret_cast<float4*>(smp) = make_float4(0.f, 0.f, 0.f, 0.f);
    smp[4] = 0.f;

    float inv = 1.0f / (s4 + 1e-16f);
    float S0 = v.x * inv, S1 = v.y * inv, S2 = v.z * inv, S3 = v.w * inv;
    float S4 = s4 * inv;

    int tn = t * NN + n;
    float xt0 = x[2 * tn], xt1 = x[2 * tn + 1];

    float P = S0*h[0] + S1*h[1] + S2*h[2] + S3*h[3] + S4*h[4]
            + xt0*h[5] + xt1*h[6] + h[7];
    float Q = S0*h[8] + S1*h[9] + S2*h[10] + S3*h[11] + S4*h[12]
            + xt0*h[13] + xt1*h[14] + h[15];

    int vo = t * (2 * LL * NN) + 2 * (l * NN + n);
    g_val[vo]     = P;
    g_val[vo + 1] = Q;
}

// ---------------- K3: GEMV — R3 config (8 warps x 2 rows) + streaming loads ----------------
__global__ void __launch_bounds__(256) gemv_kernel(const float* __restrict__ Wfc,
                                                   const float* __restrict__ bfc,
                                                   float* __restrict__ out)
{
    const int t = blockIdx.y;
    const int rowBase = blockIdx.x * 16;
    __shared__ float4 sv[1024];                    // 16 KB chunk of val

    int tid = threadIdx.x;
    int lane = tid & 31;
    int w = tid >> 5;
    int r0 = rowBase + w;
    int r1 = rowBase + 8 + w;

    const float4* val4 = reinterpret_cast<const float4*>(g_val + t * (2 * LL * NN));
    const float4* W0 = reinterpret_cast<const float4*>(Wfc + ((size_t)(t * 4096 + r0)) * 16384);
    const float4* W1 = reinterpret_cast<const float4*>(Wfc + ((size_t)(t * 4096 + r1)) * 16384);

    float4 a0 = make_float4(0.f, 0.f, 0.f, 0.f);
    float4 a1 = make_float4(0.f, 0.f, 0.f, 0.f);

#pragma unroll
    for (int c = 0; c < 4; c++) {
        for (int j = tid; j < 1024; j += 256)
            sv[j] = val4[c * 1024 + j];
        __syncthreads();

        const int base = c * 1024;
#pragma unroll 8
        for (int j = lane; j < 1024; j += 32) {
            float4 v  = sv[j];
            float4 w0 = __ldcs(&W0[base + j]);   // streaming: no-reuse 1GB scan
            float4 w1 = __ldcs(&W1[base + j]);
            a0.x = fmaf(w0.x, v.x, a0.x);
            a0.y = fmaf(w0.y, v.y, a0.y);
            a0.z = fmaf(w0.z, v.z, a0.z);
            a0.w = fmaf(w0.w, v.w, a0.w);
            a1.x = fmaf(w1.x, v.x, a1.x);
            a1.y = fmaf(w1.y, v.y, a1.y);
            a1.z = fmaf(w1.z, v.z, a1.z);
            a1.w = fmaf(w1.w, v.w, a1.w);
        }
        __syncthreads();
    }

    float s0 = (a0.x + a0.y) + (a0.z + a0.w);
    float s1 = (a1.x + a1.y) + (a1.z + a1.w);
#pragma unroll
    for (int off = 16; off > 0; off >>= 1) {
        s0 += __shfl_down_sync(0xffffffffu, s0, off);
        s1 += __shfl_down_sync(0xffffffffu, s1, off);
    }
    if (lane == 0) {
        out[t * 4096 + r0] = s0 + bfc[t * 4096 + r0];
        out[t * 4096 + r1] = s1 + bfc[t * 4096 + r1];
    }
}

// ---------------- launch: 3 kernels, single stream ----------------
extern "C" void kernel_launch(void* const* d_in, const int* in_sizes, int n_in,
                              void* d_out, int out_size)
{
    const float* x    = (const float*)d_in[0];
    const float* ea   = (const float*)d_in[1];
    const int*   src  = (const int*)  d_in[2];
    const int*   tgt  = (const int*)  d_in[3];
    const float* Wq   = (const float*)d_in[4];
    const float* bq   = (const float*)d_in[5];
    const float* Wk   = (const float*)d_in[6];
    const float* bk   = (const float*)d_in[7];
    const float* Wv   = (const float*)d_in[8];
    const float* bv   = (const float*)d_in[9];
    const float* We   = (const float*)d_in[10];
    const float* Wsk  = (const float*)d_in[11];
    const float* bsk  = (const float*)d_in[12];
    const float* Wfc  = (const float*)d_in[13];
    const float* bfc  = (const float*)d_in[14];
    float* out = (float*)d_out;

    edge_kernel<<<(TT * EE) / 512, 256>>>(x, ea, src, tgt, Wq, bq, Wk, bk, We);
    node_kernel<<<(TL * NN) / 256, 256>>>(x, Wv, bv, We, Wsk, bsk);
    gemv_kernel<<<dim3(256, TT), 256>>>(Wfc, bfc, out);
}